// round 1
// baseline (speedup 1.0000x reference)
#include <cuda_runtime.h>
#include <mma.h>

using namespace nvcuda;

#define LDA 136   // leading dim for 64x128 fp32 buffers (pad 8 floats)
#define LDS 72    // leading dim for 64-wide buffers
#define SCALE 0.17677669529663687f  // 1/sqrt(32)

__device__ float g_relbias[4 * 64 * 64];

// Pre-gather relative-position bias: relbias[h][n][m] = bias_table[rpi(n,m)][h]
__global__ void relbias_kernel(const float* __restrict__ bias_table) {
    int idx = blockIdx.x * blockDim.x + threadIdx.x;
    if (idx < 4 * 64 * 64) {
        int h = idx >> 12;
        int n = (idx >> 6) & 63;
        int m = idx & 63;
        int r = ((n >> 3) - (m >> 3) + 7) * 15 + ((n & 7) - (m & 7) + 7);
        g_relbias[idx] = bias_table[r * 4 + h];
    }
}

using FragA = wmma::fragment<wmma::matrix_a, 16, 16, 8, wmma::precision::tf32, wmma::row_major>;
using FragB = wmma::fragment<wmma::matrix_b, 16, 16, 8, wmma::precision::tf32, wmma::col_major>;
using FragC = wmma::fragment<wmma::accumulator, 16, 16, 8, float>;

__device__ __forceinline__ void cvt_a(FragA& f) {
#pragma unroll
    for (int i = 0; i < f.num_elements; i++) f.x[i] = wmma::__float_to_tf32(f.x[i]);
}
__device__ __forceinline__ void cvt_b(FragB& f) {
#pragma unroll
    for (int i = 0; i < f.num_elements; i++) f.x[i] = wmma::__float_to_tf32(f.x[i]);
}

// Warp computes a COLUMN strip: NT vertical 16x16 tiles at column-tile ni.
// B fragment loaded once per k-step (use when B is the global weight -> read once/CTA).
template <int NT, int KTOT>
__device__ __forceinline__ void gemm_colstrip(const float* __restrict__ A, int lda,
                                              const float* __restrict__ Bt, int ldb,
                                              float* __restrict__ C, int ldc, int ni) {
    FragC acc[NT];
#pragma unroll
    for (int t = 0; t < NT; t++) wmma::fill_fragment(acc[t], 0.0f);
#pragma unroll
    for (int k = 0; k < KTOT; k += 8) {
        FragB b;
        wmma::load_matrix_sync(b, Bt + k + ni * 16 * ldb, ldb);
        cvt_b(b);
#pragma unroll
        for (int t = 0; t < NT; t++) {
            FragA a;
            wmma::load_matrix_sync(a, A + t * 16 * lda + k, lda);
            cvt_a(a);
            wmma::mma_sync(acc[t], a, b, acc[t]);
        }
    }
#pragma unroll
    for (int t = 0; t < NT; t++)
        wmma::store_matrix_sync(C + t * 16 * ldc + ni * 16, acc[t], ldc, wmma::mem_row_major);
}

// Warp computes a ROW strip: NT horizontal tiles at row-tile mi, col-tiles ni0..ni0+NT-1.
// A fragment loaded once per k-step (use when A is the global weight).
template <int NT, int KTOT>
__device__ __forceinline__ void gemm_rowstrip(const float* __restrict__ A, int lda,
                                              const float* __restrict__ Bt, int ldb,
                                              float* __restrict__ C, int ldc, int mi, int ni0) {
    FragC acc[NT];
#pragma unroll
    for (int t = 0; t < NT; t++) wmma::fill_fragment(acc[t], 0.0f);
#pragma unroll
    for (int k = 0; k < KTOT; k += 8) {
        FragA a;
        wmma::load_matrix_sync(a, A + mi * 16 * lda + k, lda);
        cvt_a(a);
#pragma unroll
        for (int t = 0; t < NT; t++) {
            FragB b;
            wmma::load_matrix_sync(b, Bt + k + (ni0 + t) * 16 * ldb, ldb);
            cvt_b(b);
            wmma::mma_sync(acc[t], a, b, acc[t]);
        }
    }
#pragma unroll
    for (int t = 0; t < NT; t++)
        wmma::store_matrix_sync(C + mi * 16 * ldc + (ni0 + t) * 16, acc[t], ldc, wmma::mem_row_major);
}

__global__ void __launch_bounds__(256, 1)
win_attn_kernel(const float* __restrict__ q, const float* __restrict__ kv,
                const float* __restrict__ mask,
                const float* __restrict__ Wq, const float* __restrict__ bq,
                const float* __restrict__ Wkv, const float* __restrict__ bkv,
                const float* __restrict__ Wo, const float* __restrict__ bo,
                float* __restrict__ out) {
    extern __shared__ float smf[];
    float* sA = smf;               // [64][LDA]  q input, later final out staging
    float* sB = sA + 64 * LDA;     // [64][LDA]  kv input, later x (attn output)
    float* sC = sB + 64 * LDA;     // [64][LDA]  qh
    float* sD = sC + 64 * LDA;     // [64][LDA]  k
    float* sE = sD + 64 * LDA;     // [128][LDS] vT (v transposed: [c][n])
    float* sF = sE + 128 * LDS;    // [64][LDS]  S / P per head
    float* sM = sF + 64 * LDS;     // [64][64]   mask for this window

    const int b = blockIdx.x;
    const int tid = threadIdx.x;
    const int w = tid >> 5;
    const int lane = tid & 31;

    // ---- load q, kv, mask ----
    const float4* q4 = (const float4*)(q + (size_t)b * 8192);
    const float4* kv4 = (const float4*)(kv + (size_t)b * 8192);
    for (int i = tid; i < 2048; i += 256) {
        int row = i >> 5, c4 = i & 31;
        *(float4*)(sA + row * LDA + c4 * 4) = q4[i];
        *(float4*)(sB + row * LDA + c4 * 4) = kv4[i];
    }
    const float4* m4 = (const float4*)(mask + (size_t)(b & 4095) * 4096);
    for (int i = tid; i < 1024; i += 256) ((float4*)sM)[i] = m4[i];
    __syncthreads();

    // ---- projections ----
    // qh = q @ Wq^T   : Bt = Wq [c][k] row-major  -> read Wq once per CTA
    gemm_colstrip<4, 128>(sA, LDA, Wq, 128, sC, LDA, w);
    // k  = kv @ Wk^T  : rows 0..127 of Wkv
    gemm_colstrip<4, 128>(sB, LDA, Wkv, 128, sD, LDA, w);
    // vT = Wv @ kv^T  : A = Wkv rows 128..255 (global), B = kv (smem)
    gemm_rowstrip<4, 128>(Wkv + 128 * 128, 128, sB, LDA, sE, LDS, w, 0);
    __syncthreads();

    // ---- biases ----
    for (int i = tid; i < 8192; i += 256) {
        int row = i >> 7, c = i & 127;
        sC[row * LDA + c] += bq[c];
        sD[row * LDA + c] += bkv[c];
    }
    for (int i = tid; i < 8192; i += 256) {
        int cr = i >> 6, n = i & 63;
        sE[cr * LDS + n] += bkv[128 + cr];
    }
    __syncthreads();

    // ---- attention per head ----
#pragma unroll 1
    for (int h = 0; h < 4; h++) {
        // S = qh_h @ k_h^T  (K=32): A = sC cols h*32.., Bt = sD cols h*32..
        gemm_rowstrip<2, 32>(sC + h * 32, LDA, sD + h * 32, LDA, sF, LDS, w >> 1, (w & 1) * 2);
        __syncthreads();

        // softmax over rows with scale + rel bias + mask; each warp owns 8 rows
        const float* rb = g_relbias + h * 4096;
#pragma unroll
        for (int rr = 0; rr < 8; rr++) {
            int n = w * 8 + rr;
            float l0 = sF[n * LDS + lane] * SCALE + rb[n * 64 + lane] + sM[n * 64 + lane];
            float l1 = sF[n * LDS + lane + 32] * SCALE + rb[n * 64 + lane + 32] + sM[n * 64 + lane + 32];
            float mx = fmaxf(l0, l1);
#pragma unroll
            for (int o = 16; o; o >>= 1) mx = fmaxf(mx, __shfl_xor_sync(0xffffffffu, mx, o));
            float e0 = __expf(l0 - mx);
            float e1 = __expf(l1 - mx);
            float s = e0 + e1;
#pragma unroll
            for (int o = 16; o; o >>= 1) s += __shfl_xor_sync(0xffffffffu, s, o);
            float inv = 1.0f / s;
            sF[n * LDS + lane] = e0 * inv;
            sF[n * LDS + lane + 32] = e1 * inv;
        }
        __syncthreads();

        // x_h = P @ v_h : Bt = vT rows h*32.. (col-major view), write into sB cols h*32..
        gemm_rowstrip<1, 64>(sF, LDS, sE + h * 32 * LDS, LDS, sB + h * 32, LDA, w >> 1, w & 1);
        __syncthreads();
    }

    // ---- out = x @ Wo^T + bo ----
    gemm_colstrip<4, 128>(sB, LDA, Wo, 128, sA, LDA, w);
    __syncthreads();

    const float4* bo4 = (const float4*)bo;
    float4* out4 = (float4*)out + (size_t)b * 2048;
    for (int i = tid; i < 2048; i += 256) {
        int row = i >> 5, c4 = i & 31;
        float4 v = *(const float4*)(sA + row * LDA + c4 * 4);
        float4 bb = bo4[c4];
        v.x += bb.x; v.y += bb.y; v.z += bb.z; v.w += bb.w;
        out4[i] = v;
    }
}

extern "C" void kernel_launch(void* const* d_in, const int* in_sizes, int n_in,
                              void* d_out, int out_size) {
    const float* q          = (const float*)d_in[0];
    const float* kv         = (const float*)d_in[1];
    const float* mask       = (const float*)d_in[2];
    const float* Wq         = (const float*)d_in[3];
    const float* bq         = (const float*)d_in[4];
    const float* Wkv        = (const float*)d_in[5];
    const float* bkv        = (const float*)d_in[6];
    const float* Wo         = (const float*)d_in[7];
    const float* bo         = (const float*)d_in[8];
    const float* bias_table = (const float*)d_in[9];
    float* out = (float*)d_out;

    relbias_kernel<<<64, 256>>>(bias_table);

    size_t smem = (size_t)(4 * 64 * LDA + 128 * LDS + 64 * LDS + 64 * 64) * sizeof(float);
    cudaFuncSetAttribute(win_attn_kernel, cudaFuncAttributeMaxDynamicSharedMemorySize, (int)smem);
    win_attn_kernel<<<8192, 256, smem>>>(q, kv, mask, Wq, bq, Wkv, bkv, Wo, bo, out);
}

// round 2
// speedup vs baseline: 1.0054x; 1.0054x over previous
#include <cuda_runtime.h>
#include <mma.h>

using namespace nvcuda;

#define LDA 136   // leading dim for 64x128 fp32 buffers (pad 8 floats)
#define LDS 72    // leading dim for 64-wide buffers
#define SCALE 0.17677669529663687f  // 1/sqrt(32)

__device__ float g_relbias[4 * 64 * 64];

// Pre-gather relative-position bias: relbias[h][n][m] = bias_table[rpi(n,m)][h]
__global__ void relbias_kernel(const float* __restrict__ bias_table) {
    int idx = blockIdx.x * blockDim.x + threadIdx.x;
    if (idx < 4 * 64 * 64) {
        int h = idx >> 12;
        int n = (idx >> 6) & 63;
        int m = idx & 63;
        int r = ((n >> 3) - (m >> 3) + 7) * 15 + ((n & 7) - (m & 7) + 7);
        g_relbias[idx] = bias_table[r * 4 + h];
    }
}

using FragA = wmma::fragment<wmma::matrix_a, 16, 16, 8, wmma::precision::tf32, wmma::row_major>;
using FragB = wmma::fragment<wmma::matrix_b, 16, 16, 8, wmma::precision::tf32, wmma::col_major>;
using FragC = wmma::fragment<wmma::accumulator, 16, 16, 8, float>;

__device__ __forceinline__ void cvt_a(FragA& f) {
#pragma unroll
    for (int i = 0; i < f.num_elements; i++) f.x[i] = wmma::__float_to_tf32(f.x[i]);
}
__device__ __forceinline__ void cvt_b(FragB& f) {
#pragma unroll
    for (int i = 0; i < f.num_elements; i++) f.x[i] = wmma::__float_to_tf32(f.x[i]);
}

// Warp computes a COLUMN strip: NT vertical 16x16 tiles at column-tile ni.
// B fragment loaded once per k-step (use when B is the global weight -> read once/CTA).
template <int NT, int KTOT>
__device__ __forceinline__ void gemm_colstrip(const float* __restrict__ A, int lda,
                                              const float* __restrict__ Bt, int ldb,
                                              float* __restrict__ C, int ldc, int ni) {
    FragC acc[NT];
#pragma unroll
    for (int t = 0; t < NT; t++) wmma::fill_fragment(acc[t], 0.0f);
#pragma unroll
    for (int k = 0; k < KTOT; k += 8) {
        FragB b;
        wmma::load_matrix_sync(b, Bt + k + ni * 16 * ldb, ldb);
        cvt_b(b);
#pragma unroll
        for (int t = 0; t < NT; t++) {
            FragA a;
            wmma::load_matrix_sync(a, A + t * 16 * lda + k, lda);
            cvt_a(a);
            wmma::mma_sync(acc[t], a, b, acc[t]);
        }
    }
#pragma unroll
    for (int t = 0; t < NT; t++)
        wmma::store_matrix_sync(C + t * 16 * ldc + ni * 16, acc[t], ldc, wmma::mem_row_major);
}

// Warp computes a ROW strip: NT horizontal tiles at row-tile mi, col-tiles ni0..ni0+NT-1.
// A fragment loaded once per k-step (use when A is the global weight).
template <int NT, int KTOT>
__device__ __forceinline__ void gemm_rowstrip(const float* __restrict__ A, int lda,
                                              const float* __restrict__ Bt, int ldb,
                                              float* __restrict__ C, int ldc, int mi, int ni0) {
    FragC acc[NT];
#pragma unroll
    for (int t = 0; t < NT; t++) wmma::fill_fragment(acc[t], 0.0f);
#pragma unroll
    for (int k = 0; k < KTOT; k += 8) {
        FragA a;
        wmma::load_matrix_sync(a, A + mi * 16 * lda + k, lda);
        cvt_a(a);
#pragma unroll
        for (int t = 0; t < NT; t++) {
            FragB b;
            wmma::load_matrix_sync(b, Bt + k + (ni0 + t) * 16 * ldb, ldb);
            cvt_b(b);
            wmma::mma_sync(acc[t], a, b, acc[t]);
        }
    }
#pragma unroll
    for (int t = 0; t < NT; t++)
        wmma::store_matrix_sync(C + mi * 16 * ldc + (ni0 + t) * 16, acc[t], ldc, wmma::mem_row_major);
}

__global__ void __launch_bounds__(256, 1)
win_attn_kernel(const float* __restrict__ q, const float* __restrict__ kv,
                const float* __restrict__ mask,
                const float* __restrict__ Wq, const float* __restrict__ bq,
                const float* __restrict__ Wkv, const float* __restrict__ bkv,
                const float* __restrict__ Wo, const float* __restrict__ bo,
                float* __restrict__ out) {
    extern __shared__ float smf[];
    float* sA = smf;               // [64][LDA]  q input, later final out staging
    float* sB = sA + 64 * LDA;     // [64][LDA]  kv input, later x (attn output)
    float* sC = sB + 64 * LDA;     // [64][LDA]  qh
    float* sD = sC + 64 * LDA;     // [64][LDA]  k
    float* sE = sD + 64 * LDA;     // [128][LDS] vT (v transposed: [c][n])
    float* sF = sE + 128 * LDS;    // [64][LDS]  S / P per head
    float* sM = sF + 64 * LDS;     // [64][64]   mask for this window

    const int b = blockIdx.x;
    const int tid = threadIdx.x;
    const int w = tid >> 5;
    const int lane = tid & 31;

    // ---- load q, kv, mask ----
    const float4* q4 = (const float4*)(q + (size_t)b * 8192);
    const float4* kv4 = (const float4*)(kv + (size_t)b * 8192);
    for (int i = tid; i < 2048; i += 256) {
        int row = i >> 5, c4 = i & 31;
        *(float4*)(sA + row * LDA + c4 * 4) = q4[i];
        *(float4*)(sB + row * LDA + c4 * 4) = kv4[i];
    }
    const float4* m4 = (const float4*)(mask + (size_t)(b & 4095) * 4096);
    for (int i = tid; i < 1024; i += 256) ((float4*)sM)[i] = m4[i];
    __syncthreads();

    // ---- projections ----
    // qh = q @ Wq^T   : Bt = Wq [c][k] row-major  -> read Wq once per CTA
    gemm_colstrip<4, 128>(sA, LDA, Wq, 128, sC, LDA, w);
    // k  = kv @ Wk^T  : rows 0..127 of Wkv
    gemm_colstrip<4, 128>(sB, LDA, Wkv, 128, sD, LDA, w);
    // vT = Wv @ kv^T  : A = Wkv rows 128..255 (global), B = kv (smem)
    gemm_rowstrip<4, 128>(Wkv + 128 * 128, 128, sB, LDA, sE, LDS, w, 0);
    __syncthreads();

    // ---- biases ----
    for (int i = tid; i < 8192; i += 256) {
        int row = i >> 7, c = i & 127;
        sC[row * LDA + c] += bq[c];
        sD[row * LDA + c] += bkv[c];
    }
    for (int i = tid; i < 8192; i += 256) {
        int cr = i >> 6, n = i & 63;
        sE[cr * LDS + n] += bkv[128 + cr];
    }
    __syncthreads();

    // ---- attention per head ----
#pragma unroll 1
    for (int h = 0; h < 4; h++) {
        // S = qh_h @ k_h^T  (K=32): A = sC cols h*32.., Bt = sD cols h*32..
        gemm_rowstrip<2, 32>(sC + h * 32, LDA, sD + h * 32, LDA, sF, LDS, w >> 1, (w & 1) * 2);
        __syncthreads();

        // softmax over rows with scale + rel bias + mask; each warp owns 8 rows
        const float* rb = g_relbias + h * 4096;
#pragma unroll
        for (int rr = 0; rr < 8; rr++) {
            int n = w * 8 + rr;
            float l0 = sF[n * LDS + lane] * SCALE + rb[n * 64 + lane] + sM[n * 64 + lane];
            float l1 = sF[n * LDS + lane + 32] * SCALE + rb[n * 64 + lane + 32] + sM[n * 64 + lane + 32];
            float mx = fmaxf(l0, l1);
#pragma unroll
            for (int o = 16; o; o >>= 1) mx = fmaxf(mx, __shfl_xor_sync(0xffffffffu, mx, o));
            float e0 = __expf(l0 - mx);
            float e1 = __expf(l1 - mx);
            float s = e0 + e1;
#pragma unroll
            for (int o = 16; o; o >>= 1) s += __shfl_xor_sync(0xffffffffu, s, o);
            float inv = 1.0f / s;
            sF[n * LDS + lane] = e0 * inv;
            sF[n * LDS + lane + 32] = e1 * inv;
        }
        __syncthreads();

        // x_h = P @ v_h : Bt = vT rows h*32.. (col-major view), write into sB cols h*32..
        gemm_rowstrip<1, 64>(sF, LDS, sE + h * 32 * LDS, LDS, sB + h * 32, LDA, w >> 1, w & 1);
        __syncthreads();
    }

    // ---- out = x @ Wo^T + bo ----
    gemm_colstrip<4, 128>(sB, LDA, Wo, 128, sA, LDA, w);
    __syncthreads();

    const float4* bo4 = (const float4*)bo;
    float4* out4 = (float4*)out + (size_t)b * 2048;
    for (int i = tid; i < 2048; i += 256) {
        int row = i >> 5, c4 = i & 31;
        float4 v = *(const float4*)(sA + row * LDA + c4 * 4);
        float4 bb = bo4[c4];
        v.x += bb.x; v.y += bb.y; v.z += bb.z; v.w += bb.w;
        out4[i] = v;
    }
}

extern "C" void kernel_launch(void* const* d_in, const int* in_sizes, int n_in,
                              void* d_out, int out_size) {
    const float* q          = (const float*)d_in[0];
    const float* kv         = (const float*)d_in[1];
    const float* mask       = (const float*)d_in[2];
    const float* Wq         = (const float*)d_in[3];
    const float* bq         = (const float*)d_in[4];
    const float* Wkv        = (const float*)d_in[5];
    const float* bkv        = (const float*)d_in[6];
    const float* Wo         = (const float*)d_in[7];
    const float* bo         = (const float*)d_in[8];
    const float* bias_table = (const float*)d_in[9];
    float* out = (float*)d_out;

    relbias_kernel<<<64, 256>>>(bias_table);

    size_t smem = (size_t)(4 * 64 * LDA + 128 * LDS + 64 * LDS + 64 * 64) * sizeof(float);
    cudaFuncSetAttribute(win_attn_kernel, cudaFuncAttributeMaxDynamicSharedMemorySize, (int)smem);
    win_attn_kernel<<<8192, 256, smem>>>(q, kv, mask, Wq, bq, Wkv, bkv, Wo, bo, out);
}

// round 3
// speedup vs baseline: 1.0141x; 1.0087x over previous
#include <cuda_runtime.h>
#include <mma.h>

using namespace nvcuda;

#define LDA 136   // leading dim for 64x128 fp32 buffers (pad 8 floats)
#define LDS 72    // leading dim for 64-wide buffers
#define SCALE 0.17677669529663687f  // 1/sqrt(32)

__device__ float g_relbias[4 * 64 * 64];

// Pre-gather relative-position bias: relbias[h][n][m] = bias_table[rpi(n,m)][h]
__global__ void relbias_kernel(const float* __restrict__ bias_table) {
    int idx = blockIdx.x * blockDim.x + threadIdx.x;
    if (idx < 4 * 64 * 64) {
        int h = idx >> 12;
        int n = (idx >> 6) & 63;
        int m = idx & 63;
        int r = ((n >> 3) - (m >> 3) + 7) * 15 + ((n & 7) - (m & 7) + 7);
        g_relbias[idx] = bias_table[r * 4 + h];
    }
}

using FragA = wmma::fragment<wmma::matrix_a, 16, 16, 8, wmma::precision::tf32, wmma::row_major>;
using FragB = wmma::fragment<wmma::matrix_b, 16, 16, 8, wmma::precision::tf32, wmma::col_major>;
using FragC = wmma::fragment<wmma::accumulator, 16, 16, 8, float>;

__device__ __forceinline__ void cvt_a(FragA& f) {
#pragma unroll
    for (int i = 0; i < f.num_elements; i++) f.x[i] = wmma::__float_to_tf32(f.x[i]);
}
__device__ __forceinline__ void cvt_b(FragB& f) {
#pragma unroll
    for (int i = 0; i < f.num_elements; i++) f.x[i] = wmma::__float_to_tf32(f.x[i]);
}

// Warp computes a COLUMN strip: NT vertical 16x16 tiles at column-tile ni.
// B fragment loaded once per k-step (use when B is the global weight -> read once/CTA).
template <int NT, int KTOT>
__device__ __forceinline__ void gemm_colstrip(const float* __restrict__ A, int lda,
                                              const float* __restrict__ Bt, int ldb,
                                              float* __restrict__ C, int ldc, int ni) {
    FragC acc[NT];
#pragma unroll
    for (int t = 0; t < NT; t++) wmma::fill_fragment(acc[t], 0.0f);
#pragma unroll
    for (int k = 0; k < KTOT; k += 8) {
        FragB b;
        wmma::load_matrix_sync(b, Bt + k + ni * 16 * ldb, ldb);
        cvt_b(b);
#pragma unroll
        for (int t = 0; t < NT; t++) {
            FragA a;
            wmma::load_matrix_sync(a, A + t * 16 * lda + k, lda);
            cvt_a(a);
            wmma::mma_sync(acc[t], a, b, acc[t]);
        }
    }
#pragma unroll
    for (int t = 0; t < NT; t++)
        wmma::store_matrix_sync(C + t * 16 * ldc + ni * 16, acc[t], ldc, wmma::mem_row_major);
}

// Warp computes a ROW strip: NT horizontal tiles at row-tile mi, col-tiles ni0..ni0+NT-1.
// A fragment loaded once per k-step (use when A is the global weight).
template <int NT, int KTOT>
__device__ __forceinline__ void gemm_rowstrip(const float* __restrict__ A, int lda,
                                              const float* __restrict__ Bt, int ldb,
                                              float* __restrict__ C, int ldc, int mi, int ni0) {
    FragC acc[NT];
#pragma unroll
    for (int t = 0; t < NT; t++) wmma::fill_fragment(acc[t], 0.0f);
#pragma unroll
    for (int k = 0; k < KTOT; k += 8) {
        FragA a;
        wmma::load_matrix_sync(a, A + mi * 16 * lda + k, lda);
        cvt_a(a);
#pragma unroll
        for (int t = 0; t < NT; t++) {
            FragB b;
            wmma::load_matrix_sync(b, Bt + k + (ni0 + t) * 16 * ldb, ldb);
            cvt_b(b);
            wmma::mma_sync(acc[t], a, b, acc[t]);
        }
    }
#pragma unroll
    for (int t = 0; t < NT; t++)
        wmma::store_matrix_sync(C + mi * 16 * ldc + (ni0 + t) * 16, acc[t], ldc, wmma::mem_row_major);
}

__global__ void __launch_bounds__(256, 1)
win_attn_kernel(const float* __restrict__ q, const float* __restrict__ kv,
                const float* __restrict__ mask,
                const float* __restrict__ Wq, const float* __restrict__ bq,
                const float* __restrict__ Wkv, const float* __restrict__ bkv,
                const float* __restrict__ Wo, const float* __restrict__ bo,
                float* __restrict__ out) {
    extern __shared__ float smf[];
    float* sA = smf;               // [64][LDA]  q input, later final out staging
    float* sB = sA + 64 * LDA;     // [64][LDA]  kv input, later x (attn output)
    float* sC = sB + 64 * LDA;     // [64][LDA]  qh
    float* sD = sC + 64 * LDA;     // [64][LDA]  k
    float* sE = sD + 64 * LDA;     // [128][LDS] vT (v transposed: [c][n])
    float* sF = sE + 128 * LDS;    // [64][LDS]  S / P per head
    float* sM = sF + 64 * LDS;     // [64][64]   mask for this window

    const int b = blockIdx.x;
    const int tid = threadIdx.x;
    const int w = tid >> 5;
    const int lane = tid & 31;

    // ---- load q, kv, mask ----
    const float4* q4 = (const float4*)(q + (size_t)b * 8192);
    const float4* kv4 = (const float4*)(kv + (size_t)b * 8192);
    for (int i = tid; i < 2048; i += 256) {
        int row = i >> 5, c4 = i & 31;
        *(float4*)(sA + row * LDA + c4 * 4) = q4[i];
        *(float4*)(sB + row * LDA + c4 * 4) = kv4[i];
    }
    const float4* m4 = (const float4*)(mask + (size_t)(b & 4095) * 4096);
    for (int i = tid; i < 1024; i += 256) ((float4*)sM)[i] = m4[i];
    __syncthreads();

    // ---- projections ----
    // qh = q @ Wq^T   : Bt = Wq [c][k] row-major  -> read Wq once per CTA
    gemm_colstrip<4, 128>(sA, LDA, Wq, 128, sC, LDA, w);
    // k  = kv @ Wk^T  : rows 0..127 of Wkv
    gemm_colstrip<4, 128>(sB, LDA, Wkv, 128, sD, LDA, w);
    // vT = Wv @ kv^T  : A = Wkv rows 128..255 (global), B = kv (smem)
    gemm_rowstrip<4, 128>(Wkv + 128 * 128, 128, sB, LDA, sE, LDS, w, 0);
    __syncthreads();

    // ---- biases ----
    for (int i = tid; i < 8192; i += 256) {
        int row = i >> 7, c = i & 127;
        sC[row * LDA + c] += bq[c];
        sD[row * LDA + c] += bkv[c];
    }
    for (int i = tid; i < 8192; i += 256) {
        int cr = i >> 6, n = i & 63;
        sE[cr * LDS + n] += bkv[128 + cr];
    }
    __syncthreads();

    // ---- attention per head ----
#pragma unroll 1
    for (int h = 0; h < 4; h++) {
        // S = qh_h @ k_h^T  (K=32): A = sC cols h*32.., Bt = sD cols h*32..
        gemm_rowstrip<2, 32>(sC + h * 32, LDA, sD + h * 32, LDA, sF, LDS, w >> 1, (w & 1) * 2);
        __syncthreads();

        // softmax over rows with scale + rel bias + mask; each warp owns 8 rows
        const float* rb = g_relbias + h * 4096;
#pragma unroll
        for (int rr = 0; rr < 8; rr++) {
            int n = w * 8 + rr;
            float l0 = sF[n * LDS + lane] * SCALE + rb[n * 64 + lane] + sM[n * 64 + lane];
            float l1 = sF[n * LDS + lane + 32] * SCALE + rb[n * 64 + lane + 32] + sM[n * 64 + lane + 32];
            float mx = fmaxf(l0, l1);
#pragma unroll
            for (int o = 16; o; o >>= 1) mx = fmaxf(mx, __shfl_xor_sync(0xffffffffu, mx, o));
            float e0 = __expf(l0 - mx);
            float e1 = __expf(l1 - mx);
            float s = e0 + e1;
#pragma unroll
            for (int o = 16; o; o >>= 1) s += __shfl_xor_sync(0xffffffffu, s, o);
            float inv = 1.0f / s;
            sF[n * LDS + lane] = e0 * inv;
            sF[n * LDS + lane + 32] = e1 * inv;
        }
        __syncthreads();

        // x_h = P @ v_h : Bt = vT rows h*32.. (col-major view), write into sB cols h*32..
        gemm_rowstrip<1, 64>(sF, LDS, sE + h * 32 * LDS, LDS, sB + h * 32, LDA, w >> 1, w & 1);
        __syncthreads();
    }

    // ---- out = x @ Wo^T + bo ----
    gemm_colstrip<4, 128>(sB, LDA, Wo, 128, sA, LDA, w);
    __syncthreads();

    const float4* bo4 = (const float4*)bo;
    float4* out4 = (float4*)out + (size_t)b * 2048;
    for (int i = tid; i < 2048; i += 256) {
        int row = i >> 5, c4 = i & 31;
        float4 v = *(const float4*)(sA + row * LDA + c4 * 4);
        float4 bb = bo4[c4];
        v.x += bb.x; v.y += bb.y; v.z += bb.z; v.w += bb.w;
        out4[i] = v;
    }
}

extern "C" void kernel_launch(void* const* d_in, const int* in_sizes, int n_in,
                              void* d_out, int out_size) {
    const float* q          = (const float*)d_in[0];
    const float* kv         = (const float*)d_in[1];
    const float* mask       = (const float*)d_in[2];
    const float* Wq         = (const float*)d_in[3];
    const float* bq         = (const float*)d_in[4];
    const float* Wkv        = (const float*)d_in[5];
    const float* bkv        = (const float*)d_in[6];
    const float* Wo         = (const float*)d_in[7];
    const float* bo         = (const float*)d_in[8];
    const float* bias_table = (const float*)d_in[9];
    float* out = (float*)d_out;

    relbias_kernel<<<64, 256>>>(bias_table);

    size_t smem = (size_t)(4 * 64 * LDA + 128 * LDS + 64 * LDS + 64 * 64) * sizeof(float);
    cudaFuncSetAttribute(win_attn_kernel, cudaFuncAttributeMaxDynamicSharedMemorySize, (int)smem);
    win_attn_kernel<<<8192, 256, smem>>>(q, kv, mask, Wq, bq, Wkv, bkv, Wo, bo, out);
}

// round 4
// speedup vs baseline: 1.2528x; 1.2353x over previous
#include <cuda_runtime.h>
#include <mma.h>

using namespace nvcuda;

#define LDA 132   // leading dim for 64x128 fp32 buffers
#define LDT 68    // leading dim for vT (128x64)
#define LDP 66    // leading dim for per-head S/P buffers (64x64)
#define SCALE 0.17677669529663687f  // 1/sqrt(32)

__device__ float g_relbias[4 * 64 * 64];

__global__ void relbias_kernel(const float* __restrict__ bias_table) {
    int idx = blockIdx.x * blockDim.x + threadIdx.x;
    if (idx < 4 * 64 * 64) {
        int h = idx >> 12;
        int n = (idx >> 6) & 63;
        int m = idx & 63;
        int r = ((n >> 3) - (m >> 3) + 7) * 15 + ((n & 7) - (m & 7) + 7);
        g_relbias[idx] = bias_table[r * 4 + h];
    }
}

using FragA = wmma::fragment<wmma::matrix_a, 16, 16, 8, wmma::precision::tf32, wmma::row_major>;
using FragB = wmma::fragment<wmma::matrix_b, 16, 16, 8, wmma::precision::tf32, wmma::col_major>;
using FragC = wmma::fragment<wmma::accumulator, 16, 16, 8, float>;

__device__ __forceinline__ void cvt_a(FragA& f) {
#pragma unroll
    for (int i = 0; i < f.num_elements; i++) f.x[i] = wmma::__float_to_tf32(f.x[i]);
}
__device__ __forceinline__ void cvt_b(FragB& f) {
#pragma unroll
    for (int i = 0; i < f.num_elements; i++) f.x[i] = wmma::__float_to_tf32(f.x[i]);
}

// COLUMN strip: NT vertical tiles at row-tiles mi0..mi0+NT-1, column-tile ni.
// B fragment loaded once per k-step (use when B is the global weight).
template <int NT, int KTOT>
__device__ __forceinline__ void gemm_colstrip(const float* __restrict__ A, int lda,
                                              const float* __restrict__ Bt, int ldb,
                                              float* __restrict__ C, int ldc,
                                              int mi0, int ni) {
    FragC acc[NT];
#pragma unroll
    for (int t = 0; t < NT; t++) wmma::fill_fragment(acc[t], 0.0f);
#pragma unroll
    for (int k = 0; k < KTOT; k += 8) {
        FragB b;
        wmma::load_matrix_sync(b, Bt + k + ni * 16 * ldb, ldb);
        cvt_b(b);
#pragma unroll
        for (int t = 0; t < NT; t++) {
            FragA a;
            wmma::load_matrix_sync(a, A + (mi0 + t) * 16 * lda + k, lda);
            cvt_a(a);
            wmma::mma_sync(acc[t], a, b, acc[t]);
        }
    }
#pragma unroll
    for (int t = 0; t < NT; t++)
        wmma::store_matrix_sync(C + (mi0 + t) * 16 * ldc + ni * 16, acc[t], ldc, wmma::mem_row_major);
}

// ROW strip: NT horizontal tiles at row-tile mi, col-tiles ni0..ni0+NT-1.
// A fragment loaded once per k-step.
template <int NT, int KTOT>
__device__ __forceinline__ void gemm_rowstrip(const float* __restrict__ A, int lda,
                                              const float* __restrict__ Bt, int ldb,
                                              float* __restrict__ C, int ldc,
                                              int mi, int ni0) {
    FragC acc[NT];
#pragma unroll
    for (int t = 0; t < NT; t++) wmma::fill_fragment(acc[t], 0.0f);
#pragma unroll
    for (int k = 0; k < KTOT; k += 8) {
        FragA a;
        wmma::load_matrix_sync(a, A + mi * 16 * lda + k, lda);
        cvt_a(a);
#pragma unroll
        for (int t = 0; t < NT; t++) {
            FragB b;
            wmma::load_matrix_sync(b, Bt + k + (ni0 + t) * 16 * ldb, ldb);
            cvt_b(b);
            wmma::mma_sync(acc[t], a, b, acc[t]);
        }
    }
#pragma unroll
    for (int t = 0; t < NT; t++)
        wmma::store_matrix_sync(C + mi * 16 * ldc + (ni0 + t) * 16, acc[t], ldc, wmma::mem_row_major);
}

// smem layout (floats):
//  [0      .. 8448)   sQ   64xLDA  q input      | reused: sS (4 heads x 64xLDP = 16896)
//  [8448   .. 16896)  sKV  64xLDA  kv input     |   (sS spans sQ+sKV exactly)
//  [16896  .. 25344)  sQH  64xLDA  qh           | reused: x (attn out) after S GEMMs
//  [25344  .. 33792)  sK   64xLDA  k            | reused: final out staging
//  [33792  .. 42496)  sVT  128xLDT v transposed
//  [42496  .. 46592)  sM   64x64   mask
#define SMEM_FLOATS 46592

__global__ void __launch_bounds__(512, 1)
win_attn_kernel(const float* __restrict__ q, const float* __restrict__ kv,
                const float* __restrict__ mask,
                const float* __restrict__ Wq, const float* __restrict__ bq,
                const float* __restrict__ Wkv, const float* __restrict__ bkv,
                const float* __restrict__ Wo, const float* __restrict__ bo,
                float* __restrict__ out) {
    extern __shared__ float smf[];
    float* sQ  = smf;
    float* sKV = smf + 8448;
    float* sQH = smf + 16896;
    float* sK  = smf + 25344;
    float* sVT = smf + 33792;
    float* sM  = smf + 42496;
    float* sS  = smf;          // overlaps sQ+sKV; valid after projections

    const int b = blockIdx.x;
    const int tid = threadIdx.x;
    const int w = tid >> 5;
    const int lane = tid & 31;

    // ---- load q, kv, mask ----
    const float4* q4 = (const float4*)(q + (size_t)b * 8192);
    const float4* kv4 = (const float4*)(kv + (size_t)b * 8192);
    for (int i = tid; i < 2048; i += 512) {
        int row = i >> 5, c4 = i & 31;
        *(float4*)(sQ + row * LDA + c4 * 4) = q4[i];
        *(float4*)(sKV + row * LDA + c4 * 4) = kv4[i];
    }
    const float4* m4 = (const float4*)(mask + (size_t)(b & 4095) * 4096);
    for (int i = tid; i < 1024; i += 512) ((float4*)sM)[i] = m4[i];
    __syncthreads();

    // ---- projections (16 warps) ----
    // qh = q @ Wq^T : warp (mi0 = (w>>3)*2, ni = w&7)
    gemm_colstrip<2, 128>(sQ, LDA, Wq, 128, sQH, LDA, (w >> 3) * 2, w & 7);
    // k = kv @ Wk^T
    gemm_colstrip<2, 128>(sKV, LDA, Wkv, 128, sK, LDA, (w >> 3) * 2, w & 7);
    // vT = Wv @ kv^T : output 128x64; warp (mi = w>>1, ni0 = (w&1)*2)
    gemm_rowstrip<2, 128>(Wkv + 128 * 128, 128, sKV, LDA, sVT, LDT, w >> 1, (w & 1) * 2);
    __syncthreads();

    // ---- biases ----
    for (int i = tid; i < 8192; i += 512) {
        int row = i >> 7, c = i & 127;
        sQH[row * LDA + c] += bq[c];
        sK[row * LDA + c] += bkv[c];
    }
    for (int i = tid; i < 8192; i += 512) {
        int cr = i >> 6, n = i & 63;
        sVT[cr * LDT + n] += bkv[128 + cr];
    }
    __syncthreads();

    // ---- attention: all 4 heads concurrently (4 warps per head) ----
    const int h = w >> 2;        // head for this warp
    const int sub = w & 3;       // sub-warp within head
    float* Ph = sS + h * 64 * LDP;

    // S_h = qh_h @ k_h^T  (K=32): warp does row-tile `sub`, all 4 col-tiles
    gemm_rowstrip<4, 32>(sQH + h * 32, LDA, sK + h * 32, LDA, Ph, LDP, sub, 0);
    __syncthreads();

    // softmax: warp owns 16 rows of its head
    {
        const float* rb = g_relbias + h * 4096;
#pragma unroll
        for (int rr = 0; rr < 16; rr++) {
            int n = sub * 16 + rr;
            float l0 = Ph[n * LDP + lane] * SCALE + rb[n * 64 + lane] + sM[n * 64 + lane];
            float l1 = Ph[n * LDP + lane + 32] * SCALE + rb[n * 64 + lane + 32] + sM[n * 64 + lane + 32];
            float mx = fmaxf(l0, l1);
#pragma unroll
            for (int o = 16; o; o >>= 1) mx = fmaxf(mx, __shfl_xor_sync(0xffffffffu, mx, o));
            float e0 = __expf(l0 - mx);
            float e1 = __expf(l1 - mx);
            float s = e0 + e1;
#pragma unroll
            for (int o = 16; o; o >>= 1) s += __shfl_xor_sync(0xffffffffu, s, o);
            float inv = 1.0f / s;
            Ph[n * LDP + lane] = e0 * inv;
            Ph[n * LDP + lane + 32] = e1 * inv;
        }
    }
    __syncthreads();

    // x_h = P_h @ v_h (K=64): output 64x32 per head, into sQH cols h*32..
    // warp does row-tile `sub`, both col-tiles (NT=2)
    gemm_rowstrip<2, 64>(Ph, LDP, sVT + h * 32 * LDT, LDT, sQH + h * 32, LDA, sub, 0);
    __syncthreads();

    // ---- out = x @ Wo^T + bo ----
    gemm_colstrip<2, 128>(sQH, LDA, Wo, 128, sK, LDA, (w >> 3) * 2, w & 7);
    __syncthreads();

    const float4* bo4 = (const float4*)bo;
    float4* out4 = (float4*)out + (size_t)b * 2048;
    for (int i = tid; i < 2048; i += 512) {
        int row = i >> 5, c4 = i & 31;
        float4 v = *(const float4*)(sK + row * LDA + c4 * 4);
        float4 bb = bo4[c4];
        v.x += bb.x; v.y += bb.y; v.z += bb.z; v.w += bb.w;
        out4[i] = v;
    }
}

extern "C" void kernel_launch(void* const* d_in, const int* in_sizes, int n_in,
                              void* d_out, int out_size) {
    const float* q          = (const float*)d_in[0];
    const float* kv         = (const float*)d_in[1];
    const float* mask       = (const float*)d_in[2];
    const float* Wq         = (const float*)d_in[3];
    const float* bq         = (const float*)d_in[4];
    const float* Wkv        = (const float*)d_in[5];
    const float* bkv        = (const float*)d_in[6];
    const float* Wo         = (const float*)d_in[7];
    const float* bo         = (const float*)d_in[8];
    const float* bias_table = (const float*)d_in[9];
    float* out = (float*)d_out;

    relbias_kernel<<<64, 256>>>(bias_table);

    size_t smem = (size_t)SMEM_FLOATS * sizeof(float);
    cudaFuncSetAttribute(win_attn_kernel, cudaFuncAttributeMaxDynamicSharedMemorySize, (int)smem);
    win_attn_kernel<<<8192, 512, smem>>>(q, kv, mask, Wq, bq, Wkv, bkv, Wo, bo, out);
}